// round 2
// baseline (speedup 1.0000x reference)
#include <cuda_runtime.h>
#include <cuda_bf16.h>
#include <cstdint>
#include <math.h>

// Problem dims (fixed per reference setup_inputs)
#define NB 64
#define NT 512
#define ND 512
#define NH 1024
#define NG 4096
#define NM (NB * NT)
#define NCTA 128     // persistent grid: 128 CTAs (one per 8-column slice of H)

// ---------------------------------------------------------------------------
// Device scratch (allocation-free rule: __device__ globals)
// ---------------------------------------------------------------------------
__device__ float g_xW[(size_t)NM * NG];                       // 512 MB input projections
__device__ __nv_bfloat16 g_xh[(size_t)NM * ND], g_xl[(size_t)NM * ND];   // split x
__device__ __nv_bfloat16 g_hh[(size_t)NM * NH], g_hl[(size_t)NM * NH];   // split h history
// Pre-split, transposed weights: [N=4096][K] bf16 hi/lo
__device__ __nv_bfloat16 g_Wx0h[(size_t)NG * ND], g_Wx0l[(size_t)NG * ND];
__device__ __nv_bfloat16 g_Wh0h[(size_t)NG * NH], g_Wh0l[(size_t)NG * NH];
__device__ __nv_bfloat16 g_Wx1h[(size_t)NG * NH], g_Wx1l[(size_t)NG * NH];
__device__ __nv_bfloat16 g_Wh1h[(size_t)NG * NH], g_Wh1l[(size_t)NG * NH];
// Grid barrier state (zero-initialized; barcnt returns to 0 after every barrier)
__device__ unsigned g_barcnt = 0;
__device__ volatile unsigned g_bargen = 0;

// ---------------------------------------------------------------------------
// Helpers
// ---------------------------------------------------------------------------
__device__ __forceinline__ void cp16(uint32_t dst, const void* src) {
    asm volatile("cp.async.cg.shared.global [%0], [%1], 16;" :: "r"(dst), "l"(src));
}
__device__ __forceinline__ void cp_commit() {
    asm volatile("cp.async.commit_group;");
}
template <int N> __device__ __forceinline__ void cp_wait() {
    asm volatile("cp.async.wait_group %0;" :: "n"(N));
}

__device__ __forceinline__ void mma_bf16(float c[4], const uint32_t a[4],
                                         const uint32_t b[2]) {
    asm volatile(
        "mma.sync.aligned.m16n8k16.row.col.f32.bf16.bf16.f32 "
        "{%0,%1,%2,%3}, {%4,%5,%6,%7}, {%8,%9}, {%0,%1,%2,%3};"
        : "+f"(c[0]), "+f"(c[1]), "+f"(c[2]), "+f"(c[3])
        : "r"(a[0]), "r"(a[1]), "r"(a[2]), "r"(a[3]), "r"(b[0]), "r"(b[1]));
}

__device__ __forceinline__ void grid_sync() {
    __threadfence();
    __syncthreads();
    if (threadIdx.x == 0) {
        unsigned gen = g_bargen;
        if (atomicAdd(&g_barcnt, 1u) == NCTA - 1) {
            g_barcnt = 0;
            __threadfence();
            g_bargen = gen + 1;
        } else {
            while (g_bargen == gen) __nanosleep(32);
        }
    }
    __syncthreads();
    __threadfence();
}

// ---------------------------------------------------------------------------
// Split kernels: fp32 -> bf16 hi/lo
// ---------------------------------------------------------------------------
__global__ void split_plain(const float* __restrict__ W,
                            __nv_bfloat16* __restrict__ hi,
                            __nv_bfloat16* __restrict__ lo, int n) {
    int idx = blockIdx.x * blockDim.x + threadIdx.x;
    if (idx >= n) return;
    float v = W[idx];
    __nv_bfloat16 h = __float2bfloat16(v);
    hi[idx] = h;
    lo[idx] = __float2bfloat16(v - __bfloat162float(h));
}

// W [K][N] fp32 -> hi/lo [N][K] bf16 (transposed, split)
__global__ void split_transpose(const float* __restrict__ W,
                                __nv_bfloat16* __restrict__ hi,
                                __nv_bfloat16* __restrict__ lo,
                                int K, int N) {
    int idx = blockIdx.x * blockDim.x + threadIdx.x;
    if (idx >= K * N) return;
    int n = idx / K;
    int k = idx - n * K;
    float v = W[(size_t)k * N + n];
    __nv_bfloat16 h = __float2bfloat16(v);
    hi[idx] = h;
    lo[idx] = __float2bfloat16(v - __bfloat162float(h));
}

// ---------------------------------------------------------------------------
// Input-projection GEMM: C[M,4096] = A[M,K](bf16 hi/lo) * B[N,K](bf16 hi/lo) + bias
// CTA tile 128x64, BK=32, 256 threads (8 warps: 4(M) x 2(N), warp tile 32x32).
// ---------------------------------------------------------------------------
__global__ __launch_bounds__(256) void gemm_in(
    const __nv_bfloat16* __restrict__ Ah, const __nv_bfloat16* __restrict__ Al,
    const __nv_bfloat16* __restrict__ Bh, const __nv_bfloat16* __restrict__ Bl,
    const float* __restrict__ bias, float* __restrict__ C, int K) {
    constexpr int BM = 128, BN = 64, BK = 32, AS = BK + 8;  // AS in bf16 elems
    __shared__ __align__(16) __nv_bfloat16 sAh[BM * AS], sAl[BM * AS];
    __shared__ __align__(16) __nv_bfloat16 sBh[BN * AS], sBl[BN * AS];

    const int tid = threadIdx.x, lane = tid & 31, wid = tid >> 5;
    const int g = lane >> 2, tg = lane & 3;
    const int wm = wid & 3, wn = wid >> 2;
    const int m0 = blockIdx.y * BM, n0 = blockIdx.x * BN;

    float acc[2][4][4];
#pragma unroll
    for (int mt = 0; mt < 2; mt++)
#pragma unroll
        for (int nt = 0; nt < 4; nt++)
#pragma unroll
            for (int q = 0; q < 4; q++) acc[mt][nt][q] = 0.f;

    for (int k0 = 0; k0 < K; k0 += BK) {
        // A tile: 128 rows x 32 halves, hi + lo (uint4 = 8 halves)
#pragma unroll
        for (int i = 0; i < 2; i++) {
            int e = tid + i * 256;
            int r = e >> 2, k8 = (e & 3) << 3;
            *(uint4*)(sAh + r * AS + k8) =
                *(const uint4*)(Ah + (size_t)(m0 + r) * K + k0 + k8);
            *(uint4*)(sAl + r * AS + k8) =
                *(const uint4*)(Al + (size_t)(m0 + r) * K + k0 + k8);
        }
        // B tile: 64 rows x 32 halves
        {
            int r = tid >> 2, k8 = (tid & 3) << 3;
            *(uint4*)(sBh + r * AS + k8) =
                *(const uint4*)(Bh + (size_t)(n0 + r) * K + k0 + k8);
            *(uint4*)(sBl + r * AS + k8) =
                *(const uint4*)(Bl + (size_t)(n0 + r) * K + k0 + k8);
        }
        __syncthreads();

#pragma unroll
        for (int kk = 0; kk < BK; kk += 16) {
            uint32_t ah[2][4], al[2][4], bh[4][2], bl[4][2];
#pragma unroll
            for (int mt = 0; mt < 2; mt++) {
                int rb = wm * 32 + mt * 16;
                ah[mt][0] = *(const uint32_t*)(&sAh[(rb + g) * AS + kk + tg * 2]);
                ah[mt][1] = *(const uint32_t*)(&sAh[(rb + g + 8) * AS + kk + tg * 2]);
                ah[mt][2] = *(const uint32_t*)(&sAh[(rb + g) * AS + kk + tg * 2 + 8]);
                ah[mt][3] = *(const uint32_t*)(&sAh[(rb + g + 8) * AS + kk + tg * 2 + 8]);
                al[mt][0] = *(const uint32_t*)(&sAl[(rb + g) * AS + kk + tg * 2]);
                al[mt][1] = *(const uint32_t*)(&sAl[(rb + g + 8) * AS + kk + tg * 2]);
                al[mt][2] = *(const uint32_t*)(&sAl[(rb + g) * AS + kk + tg * 2 + 8]);
                al[mt][3] = *(const uint32_t*)(&sAl[(rb + g + 8) * AS + kk + tg * 2 + 8]);
            }
#pragma unroll
            for (int nt = 0; nt < 4; nt++) {
                int nb = wn * 32 + nt * 8 + g;
                bh[nt][0] = *(const uint32_t*)(&sBh[nb * AS + kk + tg * 2]);
                bh[nt][1] = *(const uint32_t*)(&sBh[nb * AS + kk + tg * 2 + 8]);
                bl[nt][0] = *(const uint32_t*)(&sBl[nb * AS + kk + tg * 2]);
                bl[nt][1] = *(const uint32_t*)(&sBl[nb * AS + kk + tg * 2 + 8]);
            }
#pragma unroll
            for (int mt = 0; mt < 2; mt++)
#pragma unroll
                for (int nt = 0; nt < 4; nt++) {
                    mma_bf16(acc[mt][nt], ah[mt], bh[nt]);
                    mma_bf16(acc[mt][nt], ah[mt], bl[nt]);
                    mma_bf16(acc[mt][nt], al[mt], bh[nt]);
                }
        }
        __syncthreads();
    }

#pragma unroll
    for (int mt = 0; mt < 2; mt++) {
        int row = m0 + wm * 32 + mt * 16 + g;
#pragma unroll
        for (int nt = 0; nt < 4; nt++) {
            int col = n0 + wn * 32 + nt * 8 + tg * 2;
            float b0v = bias[col], b1v = bias[col + 1];
            C[(size_t)row * NG + col]           = acc[mt][nt][0] + b0v;
            C[(size_t)row * NG + col + 1]       = acc[mt][nt][1] + b1v;
            C[(size_t)(row + 8) * NG + col]     = acc[mt][nt][2] + b0v;
            C[(size_t)(row + 8) * NG + col + 1] = acc[mt][nt][3] + b1v;
        }
    }
}

// ---------------------------------------------------------------------------
// Persistent recurrent kernel: all 512 timesteps of one layer in one launch.
// 128 CTAs; CTA owns an 8-column j-slice of H (32 gate rows: 4 gates x 8 cols).
// Wh slice resident in SMEM (hi/lo). Per step: z = xW_t + h_{t-1} @ Wh
// (M=64, N=32, K=1024), then cell update; h written as fp32 (opt) + bf16 hi/lo.
// Warp layout (8 warps): ks = wid>>2 (K-split 2), mh = (wid>>1)&1 (M half),
// np = wid&1 (N half) -> warp tile 32 rows x 16 cols x 512 K.
// ---------------------------------------------------------------------------
#define SEQ_SMEM (2 * 32 * 1032 * 2 + 2 * 2 * 64 * 72 * 2 + 2 * 64 * 32 * 4)

__global__ __launch_bounds__(256) void lstm_seq(
    const float* __restrict__ xW,                 // [B*T, 4H], row = b*NT + t
    const __nv_bfloat16* __restrict__ Wh,         // [4H][H] hi
    const __nv_bfloat16* __restrict__ Wl,         // [4H][H] lo
    __nv_bfloat16* __restrict__ hh,               // [B][T][H] hi (history)
    __nv_bfloat16* __restrict__ hl,               // [B][T][H] lo
    float* __restrict__ fout) {                   // optional fp32 out (layer 2)
    extern __shared__ __align__(16) unsigned char smem[];
    __nv_bfloat16* sWh = (__nv_bfloat16*)smem;        // 32 x 1032
    __nv_bfloat16* sWl = sWh + 32 * 1032;
    __nv_bfloat16* sAh = sWl + 32 * 1032;             // 2 bufs x 64 x 72
    __nv_bfloat16* sAl = sAh + 2 * 64 * 72;
    float* zs = (float*)(sAl + 2 * 64 * 72);          // [2][64][32]

    const int tid = threadIdx.x, lane = tid & 31, wid = tid >> 5;
    const int g = lane >> 2, tg = lane & 3;
    const int ks = wid >> 2, mh = (wid >> 1) & 1, np = wid & 1;
    const int j0 = blockIdx.x * 8;

    const uint32_t sAhB = (uint32_t)__cvta_generic_to_shared(sAh);
    const uint32_t sAlB = (uint32_t)__cvta_generic_to_shared(sAl);

    // Preload this CTA's Wh slice: rows r = gate*8 + jj -> global n = gate*1024 + j0 + jj
    for (int e = tid; e < 32 * 128; e += 256) {
        int r = e >> 7, k8 = (e & 127) << 3;
        int n = ((r >> 3) << 10) + j0 + (r & 7);
        *(uint4*)(sWh + r * 1032 + k8) = *(const uint4*)(Wh + (size_t)n * NH + k8);
        *(uint4*)(sWl + r * 1032 + k8) = *(const uint4*)(Wl + (size_t)n * NH + k8);
    }
    __syncthreads();

    float c0 = 0.f, c1 = 0.f;  // cell state: items tid and tid+256

    for (int t = 0; t < NT; t++) {
        if (t > 0) {
            const __nv_bfloat16* hsh = hh + (size_t)(t - 1) * NH;
            const __nv_bfloat16* hsl = hl + (size_t)(t - 1) * NH;

            // Issue A tile q into buffer bi (64 rows x 64 halves, hi+lo)
            auto issue = [&](int q, int bi) {
                int k0 = q * 64;
#pragma unroll
                for (int i = 0; i < 2; i++) {
                    int e = tid + i * 256;
                    int r = e >> 3, k8 = (e & 7) << 3;
                    size_t go = (size_t)r * (NT * NH) + k0 + k8;
                    uint32_t so = (uint32_t)(bi * 64 * 72 + r * 72 + k8) * 2;
                    cp16(sAhB + so, hsh + go);
                    cp16(sAlB + so, hsl + go);
                }
                cp_commit();
            };

            float acc[2][2][4];
#pragma unroll
            for (int mt = 0; mt < 2; mt++)
#pragma unroll
                for (int nt = 0; nt < 2; nt++)
#pragma unroll
                    for (int q = 0; q < 4; q++) acc[mt][nt][q] = 0.f;

            issue(0, 0);
            for (int q = 0; q < 16; q++) {
                if (q < 15) { issue(q + 1, (q + 1) & 1); cp_wait<1>(); }
                else        { cp_wait<0>(); }
                __syncthreads();

                const __nv_bfloat16* Ah = sAh + (q & 1) * 64 * 72;
                const __nv_bfloat16* Al = sAl + (q & 1) * 64 * 72;
                const int k0 = q * 64;
#pragma unroll
                for (int kq = 0; kq < 2; kq++) {
                    const int kk = ks * 32 + kq * 16;
                    uint32_t ah[2][4], al[2][4], bh[2][2], bl[2][2];
#pragma unroll
                    for (int mt = 0; mt < 2; mt++) {
                        int rb = mh * 32 + mt * 16;
                        ah[mt][0] = *(const uint32_t*)(&Ah[(rb + g) * 72 + kk + tg * 2]);
                        ah[mt][1] = *(const uint32_t*)(&Ah[(rb + g + 8) * 72 + kk + tg * 2]);
                        ah[mt][2] = *(const uint32_t*)(&Ah[(rb + g) * 72 + kk + tg * 2 + 8]);
                        ah[mt][3] = *(const uint32_t*)(&Ah[(rb + g + 8) * 72 + kk + tg * 2 + 8]);
                        al[mt][0] = *(const uint32_t*)(&Al[(rb + g) * 72 + kk + tg * 2]);
                        al[mt][1] = *(const uint32_t*)(&Al[(rb + g + 8) * 72 + kk + tg * 2]);
                        al[mt][2] = *(const uint32_t*)(&Al[(rb + g) * 72 + kk + tg * 2 + 8]);
                        al[mt][3] = *(const uint32_t*)(&Al[(rb + g + 8) * 72 + kk + tg * 2 + 8]);
                    }
#pragma unroll
                    for (int nt = 0; nt < 2; nt++) {
                        int r = np * 16 + nt * 8 + g;
                        bh[nt][0] = *(const uint32_t*)(&sWh[r * 1032 + k0 + kk + tg * 2]);
                        bh[nt][1] = *(const uint32_t*)(&sWh[r * 1032 + k0 + kk + tg * 2 + 8]);
                        bl[nt][0] = *(const uint32_t*)(&sWl[r * 1032 + k0 + kk + tg * 2]);
                        bl[nt][1] = *(const uint32_t*)(&sWl[r * 1032 + k0 + kk + tg * 2 + 8]);
                    }
#pragma unroll
                    for (int mt = 0; mt < 2; mt++)
#pragma unroll
                        for (int nt = 0; nt < 2; nt++) {
                            mma_bf16(acc[mt][nt], ah[mt], bh[nt]);
                            mma_bf16(acc[mt][nt], ah[mt], bl[nt]);
                            mma_bf16(acc[mt][nt], al[mt], bh[nt]);
                        }
                }
                __syncthreads();
            }

            // Write partial z to smem: zs[ks][row][col]
#pragma unroll
            for (int mt = 0; mt < 2; mt++) {
                int row = mh * 32 + mt * 16 + g;
#pragma unroll
                for (int nt = 0; nt < 2; nt++) {
                    int col = np * 16 + nt * 8 + tg * 2;
                    zs[(ks * 64 + row) * 32 + col]           = acc[mt][nt][0];
                    zs[(ks * 64 + row) * 32 + col + 1]       = acc[mt][nt][1];
                    zs[(ks * 64 + row + 8) * 32 + col]       = acc[mt][nt][2];
                    zs[(ks * 64 + row + 8) * 32 + col + 1]   = acc[mt][nt][3];
                }
            }
            __syncthreads();
        }

        // Elementwise LSTM cell update: 512 (b, jj) items, 2 per thread
#pragma unroll
        for (int i = 0; i < 2; i++) {
            int p = tid + i * 256;
            int b = p >> 3, jj = p & 7, j = j0 + jj;
            size_t xr = ((size_t)b * NT + t) * NG;
            float zi = xW[xr + j];
            float zf = xW[xr + NH + j];
            float zg = xW[xr + 2 * NH + j];
            float zo = xW[xr + 3 * NH + j];
            if (t > 0) {
                int bc = b * 32;
                zi += zs[bc + jj]      + zs[2048 + bc + jj];
                zf += zs[bc + 8 + jj]  + zs[2048 + bc + 8 + jj];
                zg += zs[bc + 16 + jj] + zs[2048 + bc + 16 + jj];
                zo += zs[bc + 24 + jj] + zs[2048 + bc + 24 + jj];
            }
            float iv = 1.f / (1.f + __expf(-zi));
            float fv = 1.f / (1.f + __expf(-zf));
            float gv = tanhf(zg);
            float ov = 1.f / (1.f + __expf(-zo));
            float cp = (i == 0) ? c0 : c1;
            float cn = fv * cp + iv * gv;
            if (i == 0) c0 = cn; else c1 = cn;
            float hv = ov * tanhf(cn);
            size_t ho = ((size_t)b * NT + t) * NH + j;
            __nv_bfloat16 hb = __float2bfloat16(hv);
            hh[ho] = hb;
            hl[ho] = __float2bfloat16(hv - __bfloat162float(hb));
            if (fout) fout[ho] = hv;
        }

        grid_sync();  // publish h(t) before any CTA reads it at t+1
    }
}

// ---------------------------------------------------------------------------
// kernel_launch: 9 graph nodes total.
// splits (5) -> gemm L0 -> persistent L0 -> gemm L1 -> persistent L1
// ---------------------------------------------------------------------------
extern "C" void kernel_launch(void* const* d_in, const int* in_sizes, int n_in,
                              void* d_out, int out_size) {
    (void)in_sizes; (void)n_in; (void)out_size;
    const float* x   = (const float*)d_in[0];
    const float* Wx0 = (const float*)d_in[1];
    const float* Wh0 = (const float*)d_in[2];
    const float* b0  = (const float*)d_in[3];
    const float* Wx1 = (const float*)d_in[4];
    const float* Wh1 = (const float*)d_in[5];
    const float* b1  = (const float*)d_in[6];
    float* out = (float*)d_out;

    float* xW;
    __nv_bfloat16 *xh, *xl, *hhp, *hlp;
    __nv_bfloat16 *wx0h, *wx0l, *wh0h, *wh0l, *wx1h, *wx1l, *wh1h, *wh1l;
    cudaGetSymbolAddress((void**)&xW, g_xW);
    cudaGetSymbolAddress((void**)&xh, g_xh);
    cudaGetSymbolAddress((void**)&xl, g_xl);
    cudaGetSymbolAddress((void**)&hhp, g_hh);
    cudaGetSymbolAddress((void**)&hlp, g_hl);
    cudaGetSymbolAddress((void**)&wx0h, g_Wx0h);
    cudaGetSymbolAddress((void**)&wx0l, g_Wx0l);
    cudaGetSymbolAddress((void**)&wh0h, g_Wh0h);
    cudaGetSymbolAddress((void**)&wh0l, g_Wh0l);
    cudaGetSymbolAddress((void**)&wx1h, g_Wx1h);
    cudaGetSymbolAddress((void**)&wx1l, g_Wx1l);
    cudaGetSymbolAddress((void**)&wh1h, g_Wh1h);
    cudaGetSymbolAddress((void**)&wh1l, g_Wh1l);

    cudaFuncSetAttribute(lstm_seq, cudaFuncAttributeMaxDynamicSharedMemorySize,
                         SEQ_SMEM);

    const int thr = 256;
    split_plain<<<(NM * ND + thr - 1) / thr, thr>>>(x, xh, xl, NM * ND);
    split_transpose<<<(NG * ND + thr - 1) / thr, thr>>>(Wx0, wx0h, wx0l, ND, NG);
    split_transpose<<<(NG * NH + thr - 1) / thr, thr>>>(Wh0, wh0h, wh0l, NH, NG);
    split_transpose<<<(NG * NH + thr - 1) / thr, thr>>>(Wx1, wx1h, wx1l, NH, NG);
    split_transpose<<<(NG * NH + thr - 1) / thr, thr>>>(Wh1, wh1h, wh1l, NH, NG);

    dim3 gg(NG / 64, NM / 128);  // (64, 256)

    // Layer 0: input GEMM then persistent recurrence (h -> g_hh/g_hl bf16)
    gemm_in<<<gg, 256>>>(xh, xl, wx0h, wx0l, b0, xW, ND);
    lstm_seq<<<NCTA, 256, SEQ_SMEM>>>(xW, wh0h, wh0l, hhp, hlp, nullptr);

    // Layer 1: input GEMM consumes layer-0 h (pre-split), output fp32 -> d_out
    gemm_in<<<gg, 256>>>(hhp, hlp, wx1h, wx1l, b1, xW, NH);
    lstm_seq<<<NCTA, 256, SEQ_SMEM>>>(xW, wh1h, wh1l, hhp, hlp, out);
}

// round 6
// speedup vs baseline: 1.0631x; 1.0631x over previous
#include <cuda_runtime.h>
#include <cuda_bf16.h>
#include <cstdint>
#include <math.h>

// Problem dims (fixed per reference setup_inputs)
#define NB 64
#define NT 512
#define ND 512
#define NH 1024
#define NG 4096
#define NM (NB * NT)
#define NCTA 128     // persistent grid: 128 CTAs (one per 8-column slice of H)

// ---------------------------------------------------------------------------
// Device scratch (allocation-free rule: __device__ globals)
// ---------------------------------------------------------------------------
__device__ float g_xW[(size_t)NM * NG];                       // 512 MB input projections
__device__ __nv_bfloat16 g_xh[(size_t)NM * ND], g_xl[(size_t)NM * ND];   // split x
__device__ __nv_bfloat16 g_hh[(size_t)NM * NH], g_hl[(size_t)NM * NH];   // split h history
// Pre-split, transposed weights: [N=4096][K] bf16 hi/lo
__device__ __nv_bfloat16 g_Wx0h[(size_t)NG * ND], g_Wx0l[(size_t)NG * ND];
__device__ __nv_bfloat16 g_Wh0h[(size_t)NG * NH], g_Wh0l[(size_t)NG * NH];
__device__ __nv_bfloat16 g_Wx1h[(size_t)NG * NH], g_Wx1l[(size_t)NG * NH];
__device__ __nv_bfloat16 g_Wh1h[(size_t)NG * NH], g_Wh1l[(size_t)NG * NH];
// Grid barrier state (zero-initialized; barcnt returns to 0 after every barrier)
__device__ unsigned g_barcnt = 0;
__device__ volatile unsigned g_bargen = 0;

// ---------------------------------------------------------------------------
// Helpers (NO tcgen05 — ptxas target is sm_100 plain; tcgen05 requires sm_100a)
// ---------------------------------------------------------------------------
__device__ __forceinline__ void cp16(uint32_t dst, const void* src) {
    asm volatile("cp.async.cg.shared.global [%0], [%1], 16;" :: "r"(dst), "l"(src));
}
__device__ __forceinline__ void cp_commit() {
    asm volatile("cp.async.commit_group;");
}
template <int N> __device__ __forceinline__ void cp_wait() {
    asm volatile("cp.async.wait_group %0;" :: "n"(N));
}

__device__ __forceinline__ void mma_bf16(float c[4], const uint32_t a[4],
                                         const uint32_t b[2]) {
    asm volatile(
        "mma.sync.aligned.m16n8k16.row.col.f32.bf16.bf16.f32 "
        "{%0,%1,%2,%3}, {%4,%5,%6,%7}, {%8,%9}, {%0,%1,%2,%3};"
        : "+f"(c[0]), "+f"(c[1]), "+f"(c[2]), "+f"(c[3])
        : "r"(a[0]), "r"(a[1]), "r"(a[2]), "r"(a[3]), "r"(b[0]), "r"(b[1]));
}

// Tight bounded grid barrier: no nanosleep (wakeup latency), bounded spin
// (~0.5 s worst case) so a lost arrival can't hang the container watchdog.
__device__ __forceinline__ void grid_sync() {
    __threadfence();
    __syncthreads();
    if (threadIdx.x == 0) {
        unsigned gen = g_bargen;
        if (atomicAdd(&g_barcnt, 1u) == NCTA - 1) {
            g_barcnt = 0;
            __threadfence();
            g_bargen = gen + 1;
        } else {
            for (long i = 0; i < 200000000L && g_bargen == gen; i++) { }
        }
    }
    __syncthreads();
    __threadfence();
}

// ---------------------------------------------------------------------------
// Split kernels: fp32 -> bf16 hi/lo
// ---------------------------------------------------------------------------
__global__ void split_plain(const float* __restrict__ W,
                            __nv_bfloat16* __restrict__ hi,
                            __nv_bfloat16* __restrict__ lo, int n) {
    int idx = blockIdx.x * blockDim.x + threadIdx.x;
    if (idx >= n) return;
    float v = W[idx];
    __nv_bfloat16 h = __float2bfloat16(v);
    hi[idx] = h;
    lo[idx] = __float2bfloat16(v - __bfloat162float(h));
}

// W [K][N] fp32 -> hi/lo [N][K] bf16 (transposed, split)
__global__ void split_transpose(const float* __restrict__ W,
                                __nv_bfloat16* __restrict__ hi,
                                __nv_bfloat16* __restrict__ lo,
                                int K, int N) {
    int idx = blockIdx.x * blockDim.x + threadIdx.x;
    if (idx >= K * N) return;
    int n = idx / K;
    int k = idx - n * K;
    float v = W[(size_t)k * N + n];
    __nv_bfloat16 h = __float2bfloat16(v);
    hi[idx] = h;
    lo[idx] = __float2bfloat16(v - __bfloat162float(h));
}

// ---------------------------------------------------------------------------
// Input-projection GEMM (mma.sync, proven in round 2):
// C[M,4096] = A[M,K](bf16 hi/lo) * B[N,K](bf16 hi/lo) + bias
// CTA tile 128x64, BK=32, 256 threads (8 warps: 4(M) x 2(N), warp tile 32x32).
// ---------------------------------------------------------------------------
__global__ __launch_bounds__(256) void gemm_in(
    const __nv_bfloat16* __restrict__ Ah, const __nv_bfloat16* __restrict__ Al,
    const __nv_bfloat16* __restrict__ Bh, const __nv_bfloat16* __restrict__ Bl,
    const float* __restrict__ bias, float* __restrict__ C, int K) {
    constexpr int BM = 128, BN = 64, BK = 32, AS = BK + 8;  // AS in bf16 elems
    __shared__ __align__(16) __nv_bfloat16 sAh[BM * AS], sAl[BM * AS];
    __shared__ __align__(16) __nv_bfloat16 sBh[BN * AS], sBl[BN * AS];

    const int tid = threadIdx.x, lane = tid & 31, wid = tid >> 5;
    const int g = lane >> 2, tg = lane & 3;
    const int wm = wid & 3, wn = wid >> 2;
    const int m0 = blockIdx.y * BM, n0 = blockIdx.x * BN;

    float acc[2][4][4];
#pragma unroll
    for (int mt = 0; mt < 2; mt++)
#pragma unroll
        for (int nt = 0; nt < 4; nt++)
#pragma unroll
            for (int q = 0; q < 4; q++) acc[mt][nt][q] = 0.f;

    for (int k0 = 0; k0 < K; k0 += BK) {
        // A tile: 128 rows x 32 halves, hi + lo (uint4 = 8 halves)
#pragma unroll
        for (int i = 0; i < 2; i++) {
            int e = tid + i * 256;
            int r = e >> 2, k8 = (e & 3) << 3;
            *(uint4*)(sAh + r * AS + k8) =
                *(const uint4*)(Ah + (size_t)(m0 + r) * K + k0 + k8);
            *(uint4*)(sAl + r * AS + k8) =
                *(const uint4*)(Al + (size_t)(m0 + r) * K + k0 + k8);
        }
        // B tile: 64 rows x 32 halves
        {
            int r = tid >> 2, k8 = (tid & 3) << 3;
            *(uint4*)(sBh + r * AS + k8) =
                *(const uint4*)(Bh + (size_t)(n0 + r) * K + k0 + k8);
            *(uint4*)(sBl + r * AS + k8) =
                *(const uint4*)(Bl + (size_t)(n0 + r) * K + k0 + k8);
        }
        __syncthreads();

#pragma unroll
        for (int kk = 0; kk < BK; kk += 16) {
            uint32_t ah[2][4], al[2][4], bh[4][2], bl[4][2];
#pragma unroll
            for (int mt = 0; mt < 2; mt++) {
                int rb = wm * 32 + mt * 16;
                ah[mt][0] = *(const uint32_t*)(&sAh[(rb + g) * AS + kk + tg * 2]);
                ah[mt][1] = *(const uint32_t*)(&sAh[(rb + g + 8) * AS + kk + tg * 2]);
                ah[mt][2] = *(const uint32_t*)(&sAh[(rb + g) * AS + kk + tg * 2 + 8]);
                ah[mt][3] = *(const uint32_t*)(&sAh[(rb + g + 8) * AS + kk + tg * 2 + 8]);
                al[mt][0] = *(const uint32_t*)(&sAl[(rb + g) * AS + kk + tg * 2]);
                al[mt][1] = *(const uint32_t*)(&sAl[(rb + g + 8) * AS + kk + tg * 2]);
                al[mt][2] = *(const uint32_t*)(&sAl[(rb + g) * AS + kk + tg * 2 + 8]);
                al[mt][3] = *(const uint32_t*)(&sAl[(rb + g + 8) * AS + kk + tg * 2 + 8]);
            }
#pragma unroll
            for (int nt = 0; nt < 4; nt++) {
                int nb = wn * 32 + nt * 8 + g;
                bh[nt][0] = *(const uint32_t*)(&sBh[nb * AS + kk + tg * 2]);
                bh[nt][1] = *(const uint32_t*)(&sBh[nb * AS + kk + tg * 2 + 8]);
                bl[nt][0] = *(const uint32_t*)(&sBl[nb * AS + kk + tg * 2]);
                bl[nt][1] = *(const uint32_t*)(&sBl[nb * AS + kk + tg * 2 + 8]);
            }
#pragma unroll
            for (int mt = 0; mt < 2; mt++)
#pragma unroll
                for (int nt = 0; nt < 4; nt++) {
                    mma_bf16(acc[mt][nt], ah[mt], bh[nt]);
                    mma_bf16(acc[mt][nt], ah[mt], bl[nt]);
                    mma_bf16(acc[mt][nt], al[mt], bh[nt]);
                }
        }
        __syncthreads();
    }

#pragma unroll
    for (int mt = 0; mt < 2; mt++) {
        int row = m0 + wm * 32 + mt * 16 + g;
#pragma unroll
        for (int nt = 0; nt < 4; nt++) {
            int col = n0 + wn * 32 + nt * 8 + tg * 2;
            float b0v = bias[col], b1v = bias[col + 1];
            C[(size_t)row * NG + col]           = acc[mt][nt][0] + b0v;
            C[(size_t)row * NG + col + 1]       = acc[mt][nt][1] + b1v;
            C[(size_t)(row + 8) * NG + col]     = acc[mt][nt][2] + b0v;
            C[(size_t)(row + 8) * NG + col + 1] = acc[mt][nt][3] + b1v;
        }
    }
}

// ---------------------------------------------------------------------------
// Persistent recurrent kernel: 512 timesteps of one layer in one launch.
// 128 CTAs; CTA owns an 8-column j-slice of H (32 gate rows: 4 gates x 8 cols).
// Per step: prefetch xW(t) slice into smem (cp.async, overlapped with GEMM),
// z = xW_t + h_{t-1} @ Wh (M=64, N=32, K=1024, bf16x3), cell update.
// Warp layout (8 warps): ks = wid>>2 (K-split 2), mh = (wid>>1)&1, np = wid&1.
// ---------------------------------------------------------------------------
#define SEQ_SMEM (2 * 32 * 1032 * 2 + 2 * 2 * 64 * 136 * 2 + 2 * 64 * 32 * 4 + 64 * 32 * 4)

__global__ __launch_bounds__(256) void lstm_seq(
    const float* __restrict__ xW,                 // [B*T, 4H], row = b*NT + t
    const __nv_bfloat16* __restrict__ Wh,         // [4H][H] hi
    const __nv_bfloat16* __restrict__ Wl,         // [4H][H] lo
    __nv_bfloat16* __restrict__ hh,               // [B][T][H] hi (history)
    __nv_bfloat16* __restrict__ hl,               // [B][T][H] lo
    float* __restrict__ fout) {                   // optional fp32 out (layer 2)
    extern __shared__ __align__(16) unsigned char smem[];
    __nv_bfloat16* sWh = (__nv_bfloat16*)smem;        // 32 x 1032
    __nv_bfloat16* sWl = sWh + 32 * 1032;
    __nv_bfloat16* sAh = sWl + 32 * 1032;             // 2 bufs x 64 x 136
    __nv_bfloat16* sAl = sAh + 2 * 64 * 136;
    float* zs = (float*)(sAl + 2 * 64 * 136);         // [2][64][32]
    float* sXW = zs + 2 * 64 * 32;                    // [64][32] xW staging

    const int tid = threadIdx.x, lane = tid & 31, wid = tid >> 5;
    const int g = lane >> 2, tg = lane & 3;
    const int ks = wid >> 2, mh = (wid >> 1) & 1, np = wid & 1;
    const int j0 = blockIdx.x * 8;

    const uint32_t sAhB = (uint32_t)__cvta_generic_to_shared(sAh);
    const uint32_t sAlB = (uint32_t)__cvta_generic_to_shared(sAl);
    const uint32_t sXWB = (uint32_t)__cvta_generic_to_shared(sXW);

    // Preload this CTA's Wh slice: row r = gate*8 + jj -> n = gate*1024 + j0 + jj
    for (int e = tid; e < 32 * 128; e += 256) {
        int r = e >> 7, k8 = (e & 127) << 3;
        int n = ((r >> 3) << 10) + j0 + (r & 7);
        *(uint4*)(sWh + r * 1032 + k8) = *(const uint4*)(Wh + (size_t)n * NH + k8);
        *(uint4*)(sWl + r * 1032 + k8) = *(const uint4*)(Wl + (size_t)n * NH + k8);
    }
    __syncthreads();

    float c0 = 0.f, c1 = 0.f;  // cell state: items tid and tid+256

    for (int t = 0; t < NT; t++) {
        // Prefetch this step's xW slice (64 b x 4 gates x 8 floats = 8KB).
        // Issued first so its latency hides behind the h-GEMM.
        {
            int b = tid >> 2, gate = tid & 3;
            const float* src = xW + ((size_t)b * NT + t) * NG + (gate << 10) + j0;
            uint32_t d = sXWB + (uint32_t)(b * 32 + gate * 8) * 4;
            cp16(d, src);
            cp16(d + 16, src + 4);
            cp_commit();
        }

        if (t > 0) {
            const __nv_bfloat16* hsh = hh + (size_t)(t - 1) * NH;
            const __nv_bfloat16* hsl = hl + (size_t)(t - 1) * NH;

            // stage chunk q (64 rows x 128 halves, hi+lo) into buffer bi
            auto issue = [&](int q, int bi) {
                int k0 = q * 128;
#pragma unroll
                for (int i = 0; i < 4; i++) {
                    int e = tid + i * 256;
                    int r = e >> 4, u = e & 15;
                    size_t go = (size_t)r * (NT * NH) + k0 + u * 8;
                    uint32_t so = (uint32_t)(bi * 64 * 136 + r * 136 + u * 8) * 2;
                    cp16(sAhB + so, hsh + go);
                    cp16(sAlB + so, hsl + go);
                }
                cp_commit();
            };

            float acc[2][2][4];
#pragma unroll
            for (int mt = 0; mt < 2; mt++)
#pragma unroll
                for (int nt = 0; nt < 2; nt++)
#pragma unroll
                    for (int q = 0; q < 4; q++) acc[mt][nt][q] = 0.f;

            issue(0, 0);
            for (int q = 0; q < 8; q++) {
                if (q < 7) { issue(q + 1, (q + 1) & 1); cp_wait<1>(); }
                else       { cp_wait<0>(); }
                __syncthreads();

                const __nv_bfloat16* Ah = sAh + (q & 1) * 64 * 136;
                const __nv_bfloat16* Al = sAl + (q & 1) * 64 * 136;
                const int k0 = q * 128;
#pragma unroll
                for (int kq = 0; kq < 4; kq++) {
                    const int kk = ks * 64 + kq * 16;
                    uint32_t ah[2][4], al[2][4], bh[2][2], bl[2][2];
#pragma unroll
                    for (int mt = 0; mt < 2; mt++) {
                        int rb = mh * 32 + mt * 16;
                        ah[mt][0] = *(const uint32_t*)(&Ah[(rb + g) * 136 + kk + tg * 2]);
                        ah[mt][1] = *(const uint32_t*)(&Ah[(rb + g + 8) * 136 + kk + tg * 2]);
                        ah[mt][2] = *(const uint32_t*)(&Ah[(rb + g) * 136 + kk + tg * 2 + 8]);
                        ah[mt][3] = *(const uint32_t*)(&Ah[(rb + g + 8) * 136 + kk + tg * 2 + 8]);
                        al[mt][0] = *(const uint32_t*)(&Al[(rb + g) * 136 + kk + tg * 2]);
                        al[mt][1] = *(const uint32_t*)(&Al[(rb + g + 8) * 136 + kk + tg * 2]);
                        al[mt][2] = *(const uint32_t*)(&Al[(rb + g) * 136 + kk + tg * 2 + 8]);
                        al[mt][3] = *(const uint32_t*)(&Al[(rb + g + 8) * 136 + kk + tg * 2 + 8]);
                    }
#pragma unroll
                    for (int nt = 0; nt < 2; nt++) {
                        int r = np * 16 + nt * 8 + g;
                        bh[nt][0] = *(const uint32_t*)(&sWh[r * 1032 + k0 + kk + tg * 2]);
                        bh[nt][1] = *(const uint32_t*)(&sWh[r * 1032 + k0 + kk + tg * 2 + 8]);
                        bl[nt][0] = *(const uint32_t*)(&sWl[r * 1032 + k0 + kk + tg * 2]);
                        bl[nt][1] = *(const uint32_t*)(&sWl[r * 1032 + k0 + kk + tg * 2 + 8]);
                    }
#pragma unroll
                    for (int mt = 0; mt < 2; mt++)
#pragma unroll
                        for (int nt = 0; nt < 2; nt++) {
                            mma_bf16(acc[mt][nt], ah[mt], bh[nt]);
                            mma_bf16(acc[mt][nt], ah[mt], bl[nt]);
                            mma_bf16(acc[mt][nt], al[mt], bh[nt]);
                        }
                }
                __syncthreads();
            }

            // Write partial z to smem: zs[ks][row][col]
#pragma unroll
            for (int mt = 0; mt < 2; mt++) {
                int row = mh * 32 + mt * 16 + g;
#pragma unroll
                for (int nt = 0; nt < 2; nt++) {
                    int col = np * 16 + nt * 8 + tg * 2;
                    zs[(ks * 64 + row) * 32 + col]           = acc[mt][nt][0];
                    zs[(ks * 64 + row) * 32 + col + 1]       = acc[mt][nt][1];
                    zs[(ks * 64 + row + 8) * 32 + col]       = acc[mt][nt][2];
                    zs[(ks * 64 + row + 8) * 32 + col + 1]   = acc[mt][nt][3];
                }
            }
            __syncthreads();
        } else {
            cp_wait<0>();
            __syncthreads();
        }

        // Elementwise LSTM cell update: 512 (b, jj) items, 2 per thread
#pragma unroll
        for (int i = 0; i < 2; i++) {
            int p = tid + i * 256;
            int b = p >> 3, jj = p & 7, j = j0 + jj;
            int bc32 = b * 32;
            float zi = sXW[bc32 + jj];
            float zf = sXW[bc32 + 8 + jj];
            float zg = sXW[bc32 + 16 + jj];
            float zo = sXW[bc32 + 24 + jj];
            if (t > 0) {
                zi += zs[bc32 + jj]      + zs[2048 + bc32 + jj];
                zf += zs[bc32 + 8 + jj]  + zs[2048 + bc32 + 8 + jj];
                zg += zs[bc32 + 16 + jj] + zs[2048 + bc32 + 16 + jj];
                zo += zs[bc32 + 24 + jj] + zs[2048 + bc32 + 24 + jj];
            }
            float iv = 1.f / (1.f + __expf(-zi));
            float fv = 1.f / (1.f + __expf(-zf));
            float gv = tanhf(zg);
            float ov = 1.f / (1.f + __expf(-zo));
            float cp = (i == 0) ? c0 : c1;
            float cn = fv * cp + iv * gv;
            if (i == 0) c0 = cn; else c1 = cn;
            float hv = ov * tanhf(cn);
            size_t ho = ((size_t)b * NT + t) * NH + j;
            __nv_bfloat16 hb = __float2bfloat16(hv);
            hh[ho] = hb;
            hl[ho] = __float2bfloat16(hv - __bfloat162float(hb));
            if (fout) fout[ho] = hv;
        }

        grid_sync();  // publish h(t) before any CTA reads it at t+1
    }
}

// ---------------------------------------------------------------------------
// kernel_launch: launch order puts lstm_seq L0 at index 4 so the ncu capture
// window (skip-5, capture 1) lands on it.
// ---------------------------------------------------------------------------
extern "C" void kernel_launch(void* const* d_in, const int* in_sizes, int n_in,
                              void* d_out, int out_size) {
    (void)in_sizes; (void)n_in; (void)out_size;
    const float* x   = (const float*)d_in[0];
    const float* Wx0 = (const float*)d_in[1];
    const float* Wh0 = (const float*)d_in[2];
    const float* b0  = (const float*)d_in[3];
    const float* Wx1 = (const float*)d_in[4];
    const float* Wh1 = (const float*)d_in[5];
    const float* b1  = (const float*)d_in[6];
    float* out = (float*)d_out;

    float* xW;
    __nv_bfloat16 *xh, *xl, *hhp, *hlp;
    __nv_bfloat16 *wx0h, *wx0l, *wh0h, *wh0l, *wx1h, *wx1l, *wh1h, *wh1l;
    cudaGetSymbolAddress((void**)&xW, g_xW);
    cudaGetSymbolAddress((void**)&xh, g_xh);
    cudaGetSymbolAddress((void**)&xl, g_xl);
    cudaGetSymbolAddress((void**)&hhp, g_hh);
    cudaGetSymbolAddress((void**)&hlp, g_hl);
    cudaGetSymbolAddress((void**)&wx0h, g_Wx0h);
    cudaGetSymbolAddress((void**)&wx0l, g_Wx0l);
    cudaGetSymbolAddress((void**)&wh0h, g_Wh0h);
    cudaGetSymbolAddress((void**)&wh0l, g_Wh0l);
    cudaGetSymbolAddress((void**)&wx1h, g_Wx1h);
    cudaGetSymbolAddress((void**)&wx1l, g_Wx1l);
    cudaGetSymbolAddress((void**)&wh1h, g_Wh1h);
    cudaGetSymbolAddress((void**)&wh1l, g_Wh1l);

    cudaFuncSetAttribute(lstm_seq, cudaFuncAttributeMaxDynamicSharedMemorySize,
                         SEQ_SMEM);

    const int thr = 256;
    dim3 gg(NG / 64, NM / 128);  // (64, 256)

    // Layer 0 (launch indices 0-4; index 4 = lstm_seq L0 for ncu)
    split_plain<<<(NM * ND + thr - 1) / thr, thr>>>(x, xh, xl, NM * ND);
    split_transpose<<<(NG * ND + thr - 1) / thr, thr>>>(Wx0, wx0h, wx0l, ND, NG);
    split_transpose<<<(NG * NH + thr - 1) / thr, thr>>>(Wh0, wh0h, wh0l, NH, NG);
    gemm_in<<<gg, 256>>>(xh, xl, wx0h, wx0l, b0, xW, ND);
    lstm_seq<<<NCTA, 256, SEQ_SMEM>>>(xW, wh0h, wh0l, hhp, hlp, nullptr);

    // Layer 1 (weight splits deferred until here; only needed now)
    split_transpose<<<(NG * NH + thr - 1) / thr, thr>>>(Wx1, wx1h, wx1l, NH, NG);
    split_transpose<<<(NG * NH + thr - 1) / thr, thr>>>(Wh1, wh1h, wh1l, NH, NG);
    gemm_in<<<gg, 256>>>(hhp, hlp, wx1h, wx1l, b1, xW, NH);
    lstm_seq<<<NCTA, 256, SEQ_SMEM>>>(xW, wh1h, wh1l, hhp, hlp, out);
}